// round 14
// baseline (speedup 1.0000x reference)
#include <cuda_runtime.h>
#include <cuda_bf16.h>
#include <math.h>

#define B_   64
#define S_   400
#define SX_  200
#define H_   512
#define E_   256
#define V_   50000
#define EXT_ 1000

#define NV 128
#define KC 16
#define WST 20
#define NT_ ((V_ + NV - 1) / NV)   // 391 vocab tiles

// ---------------- scratch (static device memory, no allocation) ----------------
__device__ float g_cat[B_ * 1280];          // [dec_emb | c_t_1]
__device__ float g_x[B_ * E_];              // lstm input x
__device__ float g_gates[B_ * 2048];        // LSTM gates
__device__ float g_scat[B_ * 1024];         // [h_new | c_new]
__device__ float g_sws[B_ * 1024];          // s_t_ws
__device__ float g_eE[B_ * S_];             // enc scores
__device__ float g_eX[B_ * SX_];            // xem scores
__device__ float g_attX[B_ * SX_];          // xem attention
__device__ float g_deccat[B_ * 1536];       // [h_new | c_t]
__device__ float g_z[B_ * H_];              // V1 output
__device__ float g_logits[(size_t)B_ * V_]; // vocab logits
__device__ float g_pgen[B_];                // final sigmoid p_gen
__device__ float g_vmax[NT_ * B_];          // per-tile softmax max
__device__ float g_vsum[NT_ * B_];          // per-tile softmax sumexp
__device__ float g_vM[B_];                  // per-batch max
__device__ float g_vscale[B_];              // per-batch p_gen / sum

// ---------------- helpers ----------------
__device__ __forceinline__ float tanh_fast(float x) {
    x = fminf(10.f, fmaxf(-10.f, x));
    float t = __expf(2.f * x);
    return (t - 1.f) * __frcp_rn(t + 1.f);
}

__device__ __forceinline__ float to_tf32(float x) {
    float r;
    asm("cvt.rna.tf32.f32 %0, %1;" : "=f"(r) : "f"(x));
    return r;
}

__device__ __forceinline__ void mma_tf32(float* d, const float* a, const float* b) {
    asm volatile(
        "mma.sync.aligned.m16n8k8.row.col.f32.tf32.tf32.f32 "
        "{%0,%1,%2,%3}, {%4,%5,%6,%7}, {%8,%9}, {%0,%1,%2,%3};"
        : "+f"(d[0]), "+f"(d[1]), "+f"(d[2]), "+f"(d[3])
        : "f"(a[0]), "f"(a[1]), "f"(a[2]), "f"(a[3]), "f"(b[0]), "f"(b[1]));
}

// ---------------- fused prep: cat = [emb[y], c_t_1] + all bias inits ----------------
__global__ void prep_init(const int* __restrict__ y, const float* __restrict__ emb,
                          const float* __restrict__ ct1,
                          const float* __restrict__ bxc,
                          const float* __restrict__ b_ih, const float* __restrict__ b_hh,
                          const float* __restrict__ Ws_b, const float* __restrict__ V1_b,
                          float* __restrict__ cat, float* __restrict__ px,
                          float* __restrict__ pgates, float* __restrict__ psws,
                          float* __restrict__ pz) {
    int b = blockIdx.x, t = threadIdx.x; // 256 threads
    int yb = y[b];
    cat[b * 1280 + t] = emb[(size_t)yb * E_ + t];
    for (int j = t; j < 1024; j += 256) cat[b * 1280 + 256 + j] = ct1[b * 1024 + j];
    px[b * 256 + t] = bxc[t];
    for (int j = t; j < 2048; j += 256) pgates[b * 2048 + j] = b_ih[j] + b_hh[j];
    for (int j = t; j < 1024; j += 256) psws[b * 1024 + j] = Ws_b[j];
    for (int j = t; j < 512; j += 256) pz[b * 512 + j] = V1_b[j];
}

// ---------------- tf32 MMA GEMM core ----------------
// C[64, N] (ldc) (+)= A[64, K] (lda) @ W[N, K]^T (+ bias)
// mode 0/2: direct write with bias (mode 2 also emits softmax partials);
// mode 1: atomicAdd into pre-initialized C
__device__ __forceinline__ void gemm_core(
    float* sm, const float* __restrict__ A, int lda,
    const float* __restrict__ W, const float* __restrict__ bias,
    float* __restrict__ C, int ldc, int N, int K, int n0, int ch0, int nch, int mode,
    float* __restrict__ vmax, float* __restrict__ vsum) {
    int t = threadIdx.x;
    int lane = t & 31, w = t >> 5;
    int r = lane >> 2, c = lane & 3;

    float acc[8][4];
#pragma unroll
    for (int i = 0; i < 8; i++)
#pragma unroll
        for (int j = 0; j < 4; j++) acc[i][j] = 0.f;

    int wrow0 = t >> 2, wq = t & 3;
    int zrow  = t >> 2;

    float4 wreg[2], zreg;

    // prefetch first chunk
    {
        int kc = ch0 * KC;
#pragma unroll
        for (int i = 0; i < 2; i++) {
            int gr = min(n0 + wrow0 + i * 64, N - 1);
            wreg[i] = *(const float4*)(W + (size_t)gr * K + kc + wq * 4);
        }
        zreg = *(const float4*)(A + (size_t)zrow * lda + kc + wq * 4);
    }
    {
        float* bufp = sm;
#pragma unroll
        for (int i = 0; i < 2; i++) {
            float4 v = wreg[i];
            v.x = to_tf32(v.x); v.y = to_tf32(v.y); v.z = to_tf32(v.z); v.w = to_tf32(v.w);
            *(float4*)&bufp[(wrow0 + i * 64) * WST + wq * 4] = v;
        }
        float4 v = zreg;
        v.x = to_tf32(v.x); v.y = to_tf32(v.y); v.z = to_tf32(v.z); v.w = to_tf32(v.w);
        *(float4*)&bufp[(128 + zrow) * WST + wq * 4] = v;
    }
    __syncthreads();

    for (int ci = 0; ci < nch; ci++) {
        int buf = ci & 1;
        if (ci + 1 < nch) {
            int kc = (ch0 + ci + 1) * KC;
#pragma unroll
            for (int i = 0; i < 2; i++) {
                int gr = min(n0 + wrow0 + i * 64, N - 1);
                wreg[i] = *(const float4*)(W + (size_t)gr * K + kc + wq * 4);
            }
            zreg = *(const float4*)(A + (size_t)zrow * lda + kc + wq * 4);
        }
        {
            const float* Ws = sm + buf * 3840;
            const float* Zs = Ws + 128 * WST;
#pragma unroll
            for (int ks = 0; ks < 2; ks++) {
                int k = ks * 8;
                float a[4];
                int arow = w * 16 + r;
                a[0] = Ws[arow * WST + k + c];
                a[1] = Ws[(arow + 8) * WST + k + c];
                a[2] = Ws[arow * WST + k + c + 4];
                a[3] = Ws[(arow + 8) * WST + k + c + 4];
#pragma unroll
                for (int nt = 0; nt < 8; nt++) {
                    float b[2];
                    b[0] = Zs[(nt * 8 + r) * WST + k + c];
                    b[1] = Zs[(nt * 8 + r) * WST + k + c + 4];
                    mma_tf32(acc[nt], a, b);
                }
            }
        }
        __syncthreads();
        if (ci + 1 < nch) {
            float* bufp = sm + (buf ^ 1) * 3840;
#pragma unroll
            for (int i = 0; i < 2; i++) {
                float4 v = wreg[i];
                v.x = to_tf32(v.x); v.y = to_tf32(v.y); v.z = to_tf32(v.z); v.w = to_tf32(v.w);
                *(float4*)&bufp[(wrow0 + i * 64) * WST + wq * 4] = v;
            }
            float4 v = zreg;
            v.x = to_tf32(v.x); v.y = to_tf32(v.y); v.z = to_tf32(v.z); v.w = to_tf32(v.w);
            *(float4*)&bufp[(128 + zrow) * WST + wq * 4] = v;
            __syncthreads();
        }
    }

    // epilogue: stage (N-major) tile in shared, then coalesced global op
    float blo = 0.f, bhi = 0.f;
    if (mode != 1) {
        blo = bias[min(n0 + w * 16 + r, N - 1)];
        bhi = bias[min(n0 + w * 16 + r + 8, N - 1)];
    }
    float* Cs = sm;
#pragma unroll
    for (int nt = 0; nt < 8; nt++) {
        int col = nt * 8 + 2 * c;
        Cs[(w * 16 + r) * 65 + col]         = acc[nt][0] + blo;
        Cs[(w * 16 + r) * 65 + col + 1]     = acc[nt][1] + blo;
        Cs[(w * 16 + r + 8) * 65 + col]     = acc[nt][2] + bhi;
        Cs[(w * 16 + r + 8) * 65 + col + 1] = acc[nt][3] + bhi;
    }
    __syncthreads();
    int rem = min(NV, N - n0);
    if (mode != 1) {
        for (int i = t; i < 64 * NV; i += 256) {
            int b = i >> 7, v = i & 127;
            if (v < rem) C[(size_t)b * ldc + n0 + v] = Cs[v * 65 + b];
        }
    } else {
        for (int i = t; i < 64 * NV; i += 256) {
            int b = i >> 7, v = i & 127;
            if (v < rem) atomicAdd(&C[(size_t)b * ldc + n0 + v], Cs[v * 65 + b]);
        }
    }
    if (mode == 2) {
        // per-tile softmax partials: 64 rows x 4 threads each
        int row = t >> 2, q = t & 3;
        float m = -1e30f, ssum = 0.f;
        for (int v = q; v < rem; v += 4) {
            float x = Cs[v * 65 + row];
            if (x > m) { ssum = ssum * __expf(m - x) + 1.f; m = x; }
            else ssum += __expf(x - m);
        }
#pragma unroll
        for (int o = 1; o <= 2; o <<= 1) {
            float m2 = __shfl_xor_sync(0xffffffffu, m, o);
            float s2 = __shfl_xor_sync(0xffffffffu, ssum, o);
            float M = fmaxf(m, m2);
            ssum = ssum * __expf(m - M) + s2 * __expf(m2 - M);
            m = M;
        }
        if (q == 0) {
            vmax[blockIdx.x * 64 + row] = m;
            vsum[blockIdx.x * 64 + row] = ssum;
        }
    }
}

__global__ __launch_bounds__(256, 2)
void gemm_mma(const float* __restrict__ A, int lda,
              const float* __restrict__ W,
              const float* __restrict__ bias,
              float* __restrict__ C, int ldc,
              int N, int K, int nsplit, int mode,
              float* vmax, float* vsum) {
    __shared__ float sm[128 * 65];
    int nch = (K / KC) / nsplit;
    gemm_core(sm, A, lda, W, bias, C, ldc, N, K, blockIdx.x * NV,
              blockIdx.y * nch, nch, mode, vmax, vsum);
}

// two atomic GEMMs into the same C in one launch (blockIdx.y selects operand set)
__global__ __launch_bounds__(256, 2)
void gemm_dual(const float* __restrict__ A1, int lda1, const float* __restrict__ W1,
               int K1, int ns1,
               const float* __restrict__ A2, int lda2, const float* __restrict__ W2,
               int K2, int ns2,
               float* __restrict__ C, int ldc, int N) {
    __shared__ float sm[128 * 65];
    int zy = blockIdx.y;
    if (zy < ns1) {
        int nch = (K1 / KC) / ns1;
        gemm_core(sm, A1, lda1, W1, nullptr, C, ldc, N, K1, blockIdx.x * NV,
                  zy * nch, nch, 1, nullptr, nullptr);
    } else {
        int z = zy - ns1;
        int nch = (K2 / KC) / ns2;
        gemm_core(sm, A2, lda2, W2, nullptr, C, ldc, N, K2, blockIdx.x * NV,
                  z * nch, nch, 1, nullptr, nullptr);
    }
}

// ---------------- merged: V1 GEMM (64 blocks) + p_gen (64 blocks) ----------------
__global__ __launch_bounds__(256, 2)
void v1_pgen(const float* __restrict__ deccat, const float* __restrict__ V1_W,
             float* __restrict__ z,
             const float* __restrict__ ct, const float* __restrict__ s_cat,
             const float* __restrict__ cat, const float* __restrict__ pg_W,
             const float* __restrict__ pg_b, float* __restrict__ pgen) {
    __shared__ float sm[128 * 65];
    int bx = blockIdx.x;
    if (bx < 64) {
        // V1: N=512, K=1536; tiles 0..3 (x), splits 0..15 -> nch = 96/16 = 6
        int tile = bx & 3, zsp = bx >> 2;
        gemm_core(sm, deccat, 1536, V1_W, nullptr, z, 512, 512, 1536,
                  tile * NV, zsp * 6, 6, 1, nullptr, nullptr);
    } else {
        int b = bx - 64, t = threadIdx.x;
        float s = 0.f;
        for (int j = t; j < 1024; j += 256) s += ct[b * 1024 + j] * pg_W[j];
        for (int j = t; j < 1024; j += 256) s += s_cat[b * 1024 + j] * pg_W[1024 + j];
        s += cat[b * 1280 + t] * pg_W[2048 + t];
#pragma unroll
        for (int o = 16; o > 0; o >>= 1) s += __shfl_xor_sync(0xffffffffu, s, o);
        if ((t & 31) == 0) sm[t >> 5] = s;
        __syncthreads();
        if (t == 0) {
            float tot = 0.f;
            for (int i = 0; i < 8; i++) tot += sm[i];
            pgen[b] = 1.f / (1.f + __expf(-(tot + pg_b[0])));
        }
    }
}

// ---------------- LSTM pointwise (128 blocks x 256 threads) ----------------
__global__ void lstm_pw(const float* __restrict__ gates, const float* __restrict__ c0,
                        float* __restrict__ out_h, float* __restrict__ out_c,
                        float* __restrict__ s_cat, float* __restrict__ dec_cat) {
    int b = blockIdx.x >> 1;
    int t = ((blockIdx.x & 1) << 8) + threadIdx.x; // 0..511
    const float* g = gates + b * 2048;
    float gi = g[t], gf = g[512 + t], gg = g[1024 + t], go = g[1536 + t];
    float si = 1.f / (1.f + __expf(-gi));
    float sf = 1.f / (1.f + __expf(-gf));
    float so = 1.f / (1.f + __expf(-go));
    float c = sf * c0[b * 512 + t] + si * tanh_fast(gg);
    float h = so * tanh_fast(c);
    out_h[b * 512 + t] = h;
    out_c[b * 512 + t] = c;
    s_cat[b * 1024 + t] = h;
    s_cat[b * 1024 + 512 + t] = c;
    dec_cat[b * 1536 + t] = h;
}

// ---------------- attention scores: e = tanh(features + s_ws) . v ----------------
// 16 rows per block (8 warps x 2 rows). grid (64, 38): tiles 0..24 enc, 25..37 xem
__global__ __launch_bounds__(256)
void att_e(const float* __restrict__ featE, const float* __restrict__ featX,
           const float* __restrict__ s_ws, const float* __restrict__ v_w,
           float* __restrict__ eE, float* __restrict__ eX) {
    int b = blockIdx.x;
    int tile = blockIdx.y;
    __shared__ float sw[1024], vv[1024];
    for (int j = threadIdx.x; j < 1024; j += 256) {
        sw[j] = s_ws[b * 1024 + j];
        vv[j] = v_w[j];
    }
    __syncthreads();
    int warp = threadIdx.x >> 5, lane = threadIdx.x & 31;
    const float* feat;
    float* eo;
    int L, l0;
    if (tile < 25) { l0 = tile * 16; feat = featE; eo = eE; L = S_; }
    else           { l0 = (tile - 25) * 16; feat = featX; eo = eX; L = SX_; }
#pragma unroll
    for (int rr = 0; rr < 2; rr++) {
        int l = l0 + warp * 2 + rr;
        if (l >= L) continue;
        const float* row = feat + ((size_t)b * L + l) * 1024;
        float s = 0.f;
#pragma unroll
        for (int j = lane * 4; j < 1024; j += 128) {
            float4 f4 = *(const float4*)(row + j);
            s += tanh_fast(f4.x + sw[j + 0]) * vv[j + 0];
            s += tanh_fast(f4.y + sw[j + 1]) * vv[j + 1];
            s += tanh_fast(f4.z + sw[j + 2]) * vv[j + 2];
            s += tanh_fast(f4.w + sw[j + 3]) * vv[j + 3];
        }
#pragma unroll
        for (int o = 16; o > 0; o >>= 1) s += __shfl_xor_sync(0xffffffffu, s, o);
        if (lane == 0) eo[b * L + l] = s;
    }
}

// ---------------- masked renormalized softmax (per batch row) ----------------
__device__ void softmax_row(const float* __restrict__ e, const float* __restrict__ mask,
                            float* __restrict__ out, int L) {
    __shared__ float sbuf[S_];
    __shared__ float red[9];
    int t = threadIdx.x, w = t >> 5, ln = t & 31;
    float lm = -1e30f;
    for (int j = t; j < L; j += 256) { float v = e[j]; sbuf[j] = v; lm = fmaxf(lm, v); }
#pragma unroll
    for (int o = 16; o > 0; o >>= 1) lm = fmaxf(lm, __shfl_xor_sync(0xffffffffu, lm, o));
    if (ln == 0) red[w] = lm;
    __syncthreads();
    if (t == 0) { float m = red[0]; for (int i = 1; i < 8; i++) m = fmaxf(m, red[i]); red[8] = m; }
    __syncthreads();
    float M = red[8];
    float Z = 0.f, T = 0.f;
    for (int j = t; j < L; j += 256) {
        float p = __expf(sbuf[j] - M);
        float pm = p * mask[j];
        sbuf[j] = pm;
        Z += p; T += pm;
    }
#pragma unroll
    for (int o = 16; o > 0; o >>= 1) {
        Z += __shfl_xor_sync(0xffffffffu, Z, o);
        T += __shfl_xor_sync(0xffffffffu, T, o);
    }
    __syncthreads();
    if (ln == 0) red[w] = Z;
    __syncthreads();
    if (t == 0) { float s = 0.f; for (int i = 0; i < 8; i++) s += red[i]; red[8] = s; }
    __syncthreads();
    float Zs = red[8];
    __syncthreads();
    if (ln == 0) red[w] = T;
    __syncthreads();
    if (t == 0) { float s = 0.f; for (int i = 0; i < 8; i++) s += red[i]; red[8] = s; }
    __syncthreads();
    float Ts = red[8];
    float inv = 1.f / (Ts + 1e-12f * Zs);
    for (int j = t; j < L; j += 256) out[j] = sbuf[j] * inv;
    __syncthreads();
}

__global__ void att_softmax(const float* __restrict__ eE, const float* __restrict__ eX,
                            const float* __restrict__ maskE, const float* __restrict__ maskX,
                            float* __restrict__ attE, float* __restrict__ attX) {
    int b = blockIdx.x;
    softmax_row(eE + b * S_, maskE + b * S_, attE + b * S_, S_);
    softmax_row(eX + b * SX_, maskX + b * SX_, attX + b * SX_, SX_);
}

// ---------------- context vectors + c_t = logaddexp (float4 loads) ----------------
// grid (64, 4): block owns 256 d-values (64 float4 lanes), l-range quartered
__global__ __launch_bounds__(256)
void att_c(const float* __restrict__ attE, const float* __restrict__ attX,
           const float* __restrict__ encO, const float* __restrict__ xemO,
           float* __restrict__ ct_out, float* __restrict__ dec_cat) {
    int b = blockIdx.x, dch = blockIdx.y;
    __shared__ float aE[S_], aX[SX_];
    __shared__ float4 pE[256], pX[256];
    int t = threadIdx.x;
    for (int j = t; j < S_; j += 256) aE[j] = attE[b * S_ + j];
    for (int j = t; j < SX_; j += 256) aX[j] = attX[b * SX_ + j];
    __syncthreads();
    int d0 = dch * 256 + (t & 63) * 4;
    int q = t >> 6;
    float4 sE = make_float4(0.f, 0.f, 0.f, 0.f);
    float4 sX = make_float4(0.f, 0.f, 0.f, 0.f);
    const float* pe = encO + (size_t)b * S_ * 1024 + d0;
    int l0 = q * 100, l1 = l0 + 100;
#pragma unroll 10
    for (int l = l0; l < l1; l++) {
        float4 v = *(const float4*)(pe + (size_t)l * 1024);
        float a = aE[l];
        sE.x += a * v.x; sE.y += a * v.y; sE.z += a * v.z; sE.w += a * v.w;
    }
    const float* px = xemO + (size_t)b * SX_ * 1024 + d0;
    int m0 = q * 50, m1 = m0 + 50;
#pragma unroll 10
    for (int l = m0; l < m1; l++) {
        float4 v = *(const float4*)(px + (size_t)l * 1024);
        float a = aX[l];
        sX.x += a * v.x; sX.y += a * v.y; sX.z += a * v.z; sX.w += a * v.w;
    }
    pE[t] = sE; pX[t] = sX;
    __syncthreads();
    if (t < 64) {
        float4 e0 = pE[t], e1 = pE[t + 64], e2 = pE[t + 128], e3 = pE[t + 192];
        float4 x0 = pX[t], x1 = pX[t + 64], x2 = pX[t + 128], x3 = pX[t + 192];
        float e[4] = {e0.x + e1.x + e2.x + e3.x, e0.y + e1.y + e2.y + e3.y,
                      e0.z + e1.z + e2.z + e3.z, e0.w + e1.w + e2.w + e3.w};
        float x[4] = {x0.x + x1.x + x2.x + x3.x, x0.y + x1.y + x2.y + x3.y,
                      x0.z + x1.z + x2.z + x3.z, x0.w + x1.w + x2.w + x3.w};
        float ct[4];
#pragma unroll
        for (int i = 0; i < 4; i++) {
            float m = fmaxf(e[i], x[i]);
            ct[i] = m + log1pf(expf(-fabsf(e[i] - x[i])));
        }
        float4 cv = make_float4(ct[0], ct[1], ct[2], ct[3]);
        int dd = dch * 256 + t * 4;
        *(float4*)(ct_out + b * 1024 + dd) = cv;
        *(float4*)(dec_cat + b * 1536 + 512 + dd) = cv;
    }
}

// ---------------- vocab combine: per-batch (M, scale) from tile partials ----------------
__global__ __launch_bounds__(128)
void vocab_reduce(const float* __restrict__ vmax, const float* __restrict__ vsum,
                  const float* __restrict__ pgen,
                  float* __restrict__ vM, float* __restrict__ vscale) {
    int b = blockIdx.x, t = threadIdx.x;
    float m = -1e30f, s = 0.f;
    for (int tile = t; tile < NT_; tile += 128) {
        float m2 = vmax[tile * 64 + b];
        float s2 = vsum[tile * 64 + b];
        float M = fmaxf(m, m2);
        s = s * __expf(m - M) + s2 * __expf(m2 - M);
        m = M;
    }
#pragma unroll
    for (int o = 16; o > 0; o >>= 1) {
        float m2 = __shfl_xor_sync(0xffffffffu, m, o);
        float s2 = __shfl_xor_sync(0xffffffffu, s, o);
        float M = fmaxf(m, m2);
        s = s * __expf(m - M) + s2 * __expf(m2 - M);
        m = M;
    }
    __shared__ float sm[4], ss[4];
    if ((t & 31) == 0) { sm[t >> 5] = m; ss[t >> 5] = s; }
    __syncthreads();
    if (t == 0) {
        float M = sm[0], S = ss[0];
        for (int i = 1; i < 4; i++) {
            float M2 = fmaxf(M, sm[i]);
            S = S * __expf(M - M2) + ss[i] * __expf(sm[i] - M2);
            M = M2;
        }
        vM[b] = M;
        vscale[b] = pgen[b] / S;
    }
}

// ---------------- vocab write + fused scatter-add ----------------
// grid (64, 8), 256 threads; chunk = 6375 outputs of the 51000-wide row.
// Each block writes its chunk, then applies the scatter-adds that land in it.
__global__ __launch_bounds__(256)
void vocab_write(const float* __restrict__ logits, const float* __restrict__ vM,
                 const float* __restrict__ vscale, const float* __restrict__ extz,
                 const float* __restrict__ attn, const int* __restrict__ idx,
                 const float* __restrict__ pgen, float* __restrict__ outF) {
    int b = blockIdx.x, ch = blockIdx.y, t = threadIdx.x;
    __shared__ int sidx[S_];
    __shared__ float satt[S_];
    for (int l = t; l < S_; l += 256) {
        sidx[l] = idx[b * S_ + l];
        satt[l] = attn[b * S_ + l];
    }
    float M = vM[b], scale = vscale[b];
    const float* lg = logits + (size_t)b * V_;
    float* fd = outF + (size_t)b * (V_ + EXT_);
    int j0 = ch * 6375, j1 = j0 + 6375;
    for (int j = j0 + t; j < j1; j += 256) {
        if (j < V_) fd[j] = __expf(lg[j] - M) * scale;
        else fd[j] = extz[b * EXT_ + (j - V_)];
    }
    __syncthreads();
    float w1p = 1.f - pgen[b];
    for (int l = t; l < S_; l += 256) {
        int ix = sidx[l];
        if (ix >= j0 && ix < j1) atomicAdd(&fd[ix], w1p * satt[l]);
    }
}

// ---------------- host ----------------
static float* symaddr(const void* s) {
    void* p = nullptr;
    cudaGetSymbolAddress(&p, s);
    return (float*)p;
}

extern "C" void kernel_launch(void* const* d_in, const int* in_sizes, int n_in,
                              void* d_out, int out_size) {
    const int*   y     = (const int*)d_in[0];
    const float* h0    = (const float*)d_in[1];
    const float* c0    = (const float*)d_in[2];
    const float* ct1   = (const float*)d_in[3];
    const float* encO  = (const float*)d_in[4];
    const float* encF  = (const float*)d_in[5];
    const float* maskE = (const float*)d_in[6];
    const float* xemO  = (const float*)d_in[7];
    const float* xemF  = (const float*)d_in[8];
    const float* maskX = (const float*)d_in[9];
    const float* extz  = (const float*)d_in[10];
    const int*   inpEx = (const int*)d_in[11];
    const float* emb   = (const float*)d_in[12];
    const float* Wxc   = (const float*)d_in[13];
    const float* bxc   = (const float*)d_in[14];
    const float* W_ih  = (const float*)d_in[15];
    const float* W_hh  = (const float*)d_in[16];
    const float* b_ih  = (const float*)d_in[17];
    const float* b_hh  = (const float*)d_in[18];
    const float* Ws_W  = (const float*)d_in[19];
    const float* Ws_b  = (const float*)d_in[20];
    const float* v_w   = (const float*)d_in[21];
    const float* V1_W  = (const float*)d_in[22];
    const float* V1_b  = (const float*)d_in[23];
    const float* V2_W  = (const float*)d_in[24];
    const float* V2_b  = (const float*)d_in[25];
    const float* pg_W  = (const float*)d_in[26];
    const float* pg_b  = (const float*)d_in[27];
    (void)in_sizes; (void)n_in; (void)out_size;

    float* out = (float*)d_out;
    float* o_final = out;                              // 64*51000
    float* o_h  = out + (size_t)B_ * (V_ + EXT_);      // 64*512
    float* o_c  = o_h + B_ * H_;                       // 64*512
    float* o_ct = o_c + B_ * H_;                       // 64*1024
    float* o_at = o_ct + B_ * 1024;                    // 64*400

    float* p_cat    = symaddr(g_cat);
    float* p_x      = symaddr(g_x);
    float* p_gates  = symaddr(g_gates);
    float* p_scat   = symaddr(g_scat);
    float* p_sws    = symaddr(g_sws);
    float* p_eE     = symaddr(g_eE);
    float* p_eX     = symaddr(g_eX);
    float* p_attX   = symaddr(g_attX);
    float* p_deccat = symaddr(g_deccat);
    float* p_z      = symaddr(g_z);
    float* p_logits = symaddr(g_logits);
    float* p_pgen   = symaddr(g_pgen);
    float* p_vmax   = symaddr(g_vmax);
    float* p_vsum   = symaddr(g_vsum);
    float* p_vM     = symaddr(g_vM);
    float* p_vscale = symaddr(g_vscale);

    // 0. cat = [emb[y], c_t_1] and all bias inits
    prep_init<<<B_, 256>>>(y, emb, ct1, bxc, b_ih, b_hh, Ws_b, V1_b,
                           p_cat, p_x, p_gates, p_sws, p_z);
    // 1. x = cat @ Wxc^T   (N=256, K=1280; split 16)
    gemm_mma<<<dim3(2, 16), 256>>>(p_cat, 1280, Wxc, nullptr, p_x, 256, 256, 1280, 16, 1,
                                   nullptr, nullptr);
    // 2. gates += x @ W_ih^T  and  h0 @ W_hh^T  (one dual launch)
    gemm_dual<<<dim3(16, 12), 256>>>(p_x, 256, W_ih, 256, 4,
                                     h0, 512, W_hh, 512, 8,
                                     p_gates, 2048, 2048);
    // 3. LSTM pointwise
    lstm_pw<<<128, 256>>>(p_gates, c0, o_h, o_c, p_scat, p_deccat);
    // 4. s_ws = s_cat @ Ws_W^T (N=1024, K=1024; split 16)
    gemm_mma<<<dim3(8, 16), 256>>>(p_scat, 1024, Ws_W, nullptr, p_sws, 1024, 1024, 1024, 16, 1,
                                   nullptr, nullptr);
    // 5. attention scores
    att_e<<<dim3(B_, 38), 256>>>(encF, xemF, p_sws, v_w, p_eE, p_eX);
    // 6. masked renormalized softmax
    att_softmax<<<B_, 256>>>(p_eE, p_eX, maskE, maskX, o_at, p_attX);
    // 7. contexts + c_t = logaddexp (float4)
    att_c<<<dim3(B_, 4), 256>>>(o_at, p_attX, encO, xemO, o_ct, p_deccat);
    // 8. z = dec_cat @ V1_W^T  +  p_gen (merged fat launch)
    v1_pgen<<<128, 256>>>(p_deccat, V1_W, p_z, o_ct, p_scat, p_cat, pg_W, pg_b, p_pgen);
    // 9. logits = z @ V2_W^T + V2_b (tf32 MMA) + per-tile softmax partials
    gemm_mma<<<dim3(NT_, 1), 256>>>(p_z, 512, V2_W, V2_b, p_logits, V_, V_, 512, 1, 2,
                                    p_vmax, p_vsum);
    // 10. combine partials -> per-batch M, scale
    vocab_reduce<<<B_, 128>>>(p_vmax, p_vsum, p_pgen, p_vM, p_vscale);
    // 11. write final vocab dist + ext zeros + fused scatter-add
    vocab_write<<<dim3(B_, 8), 256>>>(p_logits, p_vM, p_vscale, extz, o_at, inpEx,
                                      p_pgen, o_final);
}

// round 17
// speedup vs baseline: 1.0971x; 1.0971x over previous
#include <cuda_runtime.h>
#include <cuda_bf16.h>
#include <math.h>

#define B_   64
#define S_   400
#define SX_  200
#define H_   512
#define E_   256
#define V_   50000
#define EXT_ 1000

#define NV 128
#define KC 16
#define WST 20
#define NT_ ((V_ + NV - 1) / NV)   // 391 vocab tiles

// ---------------- scratch (static device memory, no allocation) ----------------
__device__ float g_cat[B_ * 1280];          // [dec_emb | c_t_1]
__device__ float g_x[B_ * E_];              // lstm input x
__device__ float g_gates[B_ * 2048];        // LSTM gates
__device__ float g_scat[B_ * 1024];         // [h_new | c_new]
__device__ float g_sws[B_ * 1024];          // s_t_ws
__device__ float g_eE[B_ * S_];             // enc scores
__device__ float g_eX[B_ * SX_];            // xem scores
__device__ float g_attX[B_ * SX_];          // xem attention
__device__ float g_deccat[B_ * 1536];       // [h_new | c_t]
__device__ float g_z[B_ * H_];              // V1 output
__device__ float g_logits[(size_t)B_ * V_]; // vocab logits
__device__ float g_pgen[B_];                // final sigmoid p_gen
__device__ float g_vmax[NT_ * B_];          // per-tile softmax max
__device__ float g_vsum[NT_ * B_];          // per-tile softmax sumexp
__device__ float g_vM[B_];                  // per-batch max
__device__ float g_vscale[B_];              // per-batch p_gen / sum

// ---------------- helpers ----------------
__device__ __forceinline__ float tanh_fast(float x) {
    x = fminf(10.f, fmaxf(-10.f, x));
    float t = __expf(2.f * x);
    return (t - 1.f) * __frcp_rn(t + 1.f);
}

// HW tanh (MUFU.TANH, sm_75+): 1 MUFU op, ~2^-10.8 rel err
__device__ __forceinline__ float tanh_hw(float x) {
    float r;
    asm("tanh.approx.f32 %0, %1;" : "=f"(r) : "f"(x));
    return r;
}

__device__ __forceinline__ float to_tf32(float x) {
    float r;
    asm("cvt.rna.tf32.f32 %0, %1;" : "=f"(r) : "f"(x));
    return r;
}

__device__ __forceinline__ void mma_tf32(float* d, const float* a, const float* b) {
    asm volatile(
        "mma.sync.aligned.m16n8k8.row.col.f32.tf32.tf32.f32 "
        "{%0,%1,%2,%3}, {%4,%5,%6,%7}, {%8,%9}, {%0,%1,%2,%3};"
        : "+f"(d[0]), "+f"(d[1]), "+f"(d[2]), "+f"(d[3])
        : "f"(a[0]), "f"(a[1]), "f"(a[2]), "f"(a[3]), "f"(b[0]), "f"(b[1]));
}

// ---------------- fused prep: cat = [emb[y], c_t_1] + all bias inits ----------------
__global__ void prep_init(const int* __restrict__ y, const float* __restrict__ emb,
                          const float* __restrict__ ct1,
                          const float* __restrict__ bxc,
                          const float* __restrict__ b_ih, const float* __restrict__ b_hh,
                          const float* __restrict__ Ws_b, const float* __restrict__ V1_b,
                          float* __restrict__ cat, float* __restrict__ px,
                          float* __restrict__ pgates, float* __restrict__ psws,
                          float* __restrict__ pz) {
    int b = blockIdx.x, t = threadIdx.x; // 256 threads
    int yb = y[b];
    cat[b * 1280 + t] = emb[(size_t)yb * E_ + t];
    for (int j = t; j < 1024; j += 256) cat[b * 1280 + 256 + j] = ct1[b * 1024 + j];
    px[b * 256 + t] = bxc[t];
    for (int j = t; j < 2048; j += 256) pgates[b * 2048 + j] = b_ih[j] + b_hh[j];
    for (int j = t; j < 1024; j += 256) psws[b * 1024 + j] = Ws_b[j];
    for (int j = t; j < 512; j += 256) pz[b * 512 + j] = V1_b[j];
}

// ---------------- tf32 MMA GEMM core ----------------
// C[64, N] (ldc) (+)= A[64, K] (lda) @ W[N, K]^T (+ bias)
// mode 0/2: direct write with bias (mode 2 also emits softmax partials);
// mode 1: atomicAdd into pre-initialized C
__device__ __forceinline__ void gemm_core(
    float* sm, const float* __restrict__ A, int lda,
    const float* __restrict__ W, const float* __restrict__ bias,
    float* __restrict__ C, int ldc, int N, int K, int n0, int ch0, int nch, int mode,
    float* __restrict__ vmax, float* __restrict__ vsum) {
    int t = threadIdx.x;
    int lane = t & 31, w = t >> 5;
    int r = lane >> 2, c = lane & 3;

    float acc[8][4];
#pragma unroll
    for (int i = 0; i < 8; i++)
#pragma unroll
        for (int j = 0; j < 4; j++) acc[i][j] = 0.f;

    int wrow0 = t >> 2, wq = t & 3;
    int zrow  = t >> 2;

    float4 wreg[2], zreg;

    // prefetch first chunk
    {
        int kc = ch0 * KC;
#pragma unroll
        for (int i = 0; i < 2; i++) {
            int gr = min(n0 + wrow0 + i * 64, N - 1);
            wreg[i] = *(const float4*)(W + (size_t)gr * K + kc + wq * 4);
        }
        zreg = *(const float4*)(A + (size_t)zrow * lda + kc + wq * 4);
    }
    {
        float* bufp = sm;
#pragma unroll
        for (int i = 0; i < 2; i++) {
            float4 v = wreg[i];
            v.x = to_tf32(v.x); v.y = to_tf32(v.y); v.z = to_tf32(v.z); v.w = to_tf32(v.w);
            *(float4*)&bufp[(wrow0 + i * 64) * WST + wq * 4] = v;
        }
        float4 v = zreg;
        v.x = to_tf32(v.x); v.y = to_tf32(v.y); v.z = to_tf32(v.z); v.w = to_tf32(v.w);
        *(float4*)&bufp[(128 + zrow) * WST + wq * 4] = v;
    }
    __syncthreads();

    for (int ci = 0; ci < nch; ci++) {
        int buf = ci & 1;
        if (ci + 1 < nch) {
            int kc = (ch0 + ci + 1) * KC;
#pragma unroll
            for (int i = 0; i < 2; i++) {
                int gr = min(n0 + wrow0 + i * 64, N - 1);
                wreg[i] = *(const float4*)(W + (size_t)gr * K + kc + wq * 4);
            }
            zreg = *(const float4*)(A + (size_t)zrow * lda + kc + wq * 4);
        }
        {
            const float* Ws = sm + buf * 3840;
            const float* Zs = Ws + 128 * WST;
#pragma unroll
            for (int ks = 0; ks < 2; ks++) {
                int k = ks * 8;
                float a[4];
                int arow = w * 16 + r;
                a[0] = Ws[arow * WST + k + c];
                a[1] = Ws[(arow + 8) * WST + k + c];
                a[2] = Ws[arow * WST + k + c + 4];
                a[3] = Ws[(arow + 8) * WST + k + c + 4];
#pragma unroll
                for (int nt = 0; nt < 8; nt++) {
                    float b[2];
                    b[0] = Zs[(nt * 8 + r) * WST + k + c];
                    b[1] = Zs[(nt * 8 + r) * WST + k + c + 4];
                    mma_tf32(acc[nt], a, b);
                }
            }
        }
        __syncthreads();
        if (ci + 1 < nch) {
            float* bufp = sm + (buf ^ 1) * 3840;
#pragma unroll
            for (int i = 0; i < 2; i++) {
                float4 v = wreg[i];
                v.x = to_tf32(v.x); v.y = to_tf32(v.y); v.z = to_tf32(v.z); v.w = to_tf32(v.w);
                *(float4*)&bufp[(wrow0 + i * 64) * WST + wq * 4] = v;
            }
            float4 v = zreg;
            v.x = to_tf32(v.x); v.y = to_tf32(v.y); v.z = to_tf32(v.z); v.w = to_tf32(v.w);
            *(float4*)&bufp[(128 + zrow) * WST + wq * 4] = v;
            __syncthreads();
        }
    }

    // epilogue: stage (N-major) tile in shared, then coalesced global op
    float blo = 0.f, bhi = 0.f;
    if (mode != 1) {
        blo = bias[min(n0 + w * 16 + r, N - 1)];
        bhi = bias[min(n0 + w * 16 + r + 8, N - 1)];
    }
    float* Cs = sm;
#pragma unroll
    for (int nt = 0; nt < 8; nt++) {
        int col = nt * 8 + 2 * c;
        Cs[(w * 16 + r) * 65 + col]         = acc[nt][0] + blo;
        Cs[(w * 16 + r) * 65 + col + 1]     = acc[nt][1] + blo;
        Cs[(w * 16 + r + 8) * 65 + col]     = acc[nt][2] + bhi;
        Cs[(w * 16 + r + 8) * 65 + col + 1] = acc[nt][3] + bhi;
    }
    __syncthreads();
    int rem = min(NV, N - n0);
    if (mode != 1) {
        for (int i = t; i < 64 * NV; i += 256) {
            int b = i >> 7, v = i & 127;
            if (v < rem) C[(size_t)b * ldc + n0 + v] = Cs[v * 65 + b];
        }
    } else {
        for (int i = t; i < 64 * NV; i += 256) {
            int b = i >> 7, v = i & 127;
            if (v < rem) atomicAdd(&C[(size_t)b * ldc + n0 + v], Cs[v * 65 + b]);
        }
    }
    if (mode == 2) {
        // per-tile softmax partials: 64 rows x 4 threads each
        int row = t >> 2, q = t & 3;
        float m = -1e30f, ssum = 0.f;
        for (int v = q; v < rem; v += 4) {
            float x = Cs[v * 65 + row];
            if (x > m) { ssum = ssum * __expf(m - x) + 1.f; m = x; }
            else ssum += __expf(x - m);
        }
#pragma unroll
        for (int o = 1; o <= 2; o <<= 1) {
            float m2 = __shfl_xor_sync(0xffffffffu, m, o);
            float s2 = __shfl_xor_sync(0xffffffffu, ssum, o);
            float M = fmaxf(m, m2);
            ssum = ssum * __expf(m - M) + s2 * __expf(m2 - M);
            m = M;
        }
        if (q == 0) {
            vmax[blockIdx.x * 64 + row] = m;
            vsum[blockIdx.x * 64 + row] = ssum;
        }
    }
}

__global__ __launch_bounds__(256, 2)
void gemm_mma(const float* __restrict__ A, int lda,
              const float* __restrict__ W,
              const float* __restrict__ bias,
              float* __restrict__ C, int ldc,
              int N, int K, int nsplit, int mode,
              float* vmax, float* vsum) {
    __shared__ float sm[128 * 65];
    int nch = (K / KC) / nsplit;
    gemm_core(sm, A, lda, W, bias, C, ldc, N, K, blockIdx.x * NV,
              blockIdx.y * nch, nch, mode, vmax, vsum);
}

// two atomic GEMMs into the same C in one launch (blockIdx.y selects operand set)
__global__ __launch_bounds__(256, 2)
void gemm_dual(const float* __restrict__ A1, int lda1, const float* __restrict__ W1,
               int K1, int ns1,
               const float* __restrict__ A2, int lda2, const float* __restrict__ W2,
               int K2, int ns2,
               float* __restrict__ C, int ldc, int N) {
    __shared__ float sm[128 * 65];
    int zy = blockIdx.y;
    if (zy < ns1) {
        int nch = (K1 / KC) / ns1;
        gemm_core(sm, A1, lda1, W1, nullptr, C, ldc, N, K1, blockIdx.x * NV,
                  zy * nch, nch, 1, nullptr, nullptr);
    } else {
        int z = zy - ns1;
        int nch = (K2 / KC) / ns2;
        gemm_core(sm, A2, lda2, W2, nullptr, C, ldc, N, K2, blockIdx.x * NV,
                  z * nch, nch, 1, nullptr, nullptr);
    }
}

// ---------------- merged: V1 GEMM (64 blocks) + p_gen (64 blocks) ----------------
__global__ __launch_bounds__(256, 2)
void v1_pgen(const float* __restrict__ deccat, const float* __restrict__ V1_W,
             float* __restrict__ z,
             const float* __restrict__ ct, const float* __restrict__ s_cat,
             const float* __restrict__ cat, const float* __restrict__ pg_W,
             const float* __restrict__ pg_b, float* __restrict__ pgen) {
    __shared__ float sm[128 * 65];
    int bx = blockIdx.x;
    if (bx < 64) {
        // V1: N=512, K=1536; tiles 0..3 (x), splits 0..15 -> nch = 96/16 = 6
        int tile = bx & 3, zsp = bx >> 2;
        gemm_core(sm, deccat, 1536, V1_W, nullptr, z, 512, 512, 1536,
                  tile * NV, zsp * 6, 6, 1, nullptr, nullptr);
    } else {
        int b = bx - 64, t = threadIdx.x;
        float s = 0.f;
        for (int j = t; j < 1024; j += 256) s += ct[b * 1024 + j] * pg_W[j];
        for (int j = t; j < 1024; j += 256) s += s_cat[b * 1024 + j] * pg_W[1024 + j];
        s += cat[b * 1280 + t] * pg_W[2048 + t];
#pragma unroll
        for (int o = 16; o > 0; o >>= 1) s += __shfl_xor_sync(0xffffffffu, s, o);
        if ((t & 31) == 0) sm[t >> 5] = s;
        __syncthreads();
        if (t == 0) {
            float tot = 0.f;
            for (int i = 0; i < 8; i++) tot += sm[i];
            pgen[b] = 1.f / (1.f + __expf(-(tot + pg_b[0])));
        }
    }
}

// ---------------- LSTM pointwise ----------------
__global__ void lstm_pw(const float* __restrict__ gates, const float* __restrict__ c0,
                        float* __restrict__ out_h, float* __restrict__ out_c,
                        float* __restrict__ s_cat, float* __restrict__ dec_cat) {
    int b = blockIdx.x, t = threadIdx.x; // 512 threads
    const float* g = gates + b * 2048;
    float gi = g[t], gf = g[512 + t], gg = g[1024 + t], go = g[1536 + t];
    float si = 1.f / (1.f + __expf(-gi));
    float sf = 1.f / (1.f + __expf(-gf));
    float so = 1.f / (1.f + __expf(-go));
    float c = sf * c0[b * 512 + t] + si * tanh_fast(gg);
    float h = so * tanh_fast(c);
    out_h[b * 512 + t] = h;
    out_c[b * 512 + t] = c;
    s_cat[b * 1024 + t] = h;
    s_cat[b * 1024 + 512 + t] = c;
    dec_cat[b * 1536 + t] = h;
}

// ---------------- attention scores: e = tanh(features + s_ws) . v ----------------
// 16 rows per block (8 warps x 2 rows). grid (64, 38): tiles 0..24 enc, 25..37 xem
// HW tanh (MUFU.TANH): 1 MUFU op per element vs 2+ for exp/rcp-based tanh
__global__ __launch_bounds__(256)
void att_e(const float* __restrict__ featE, const float* __restrict__ featX,
           const float* __restrict__ s_ws, const float* __restrict__ v_w,
           float* __restrict__ eE, float* __restrict__ eX) {
    int b = blockIdx.x;
    int tile = blockIdx.y;
    __shared__ float sw[1024], vv[1024];
    for (int j = threadIdx.x; j < 1024; j += 256) {
        sw[j] = s_ws[b * 1024 + j];
        vv[j] = v_w[j];
    }
    __syncthreads();
    int warp = threadIdx.x >> 5, lane = threadIdx.x & 31;
    const float* feat;
    float* eo;
    int L, l0;
    if (tile < 25) { l0 = tile * 16; feat = featE; eo = eE; L = S_; }
    else           { l0 = (tile - 25) * 16; feat = featX; eo = eX; L = SX_; }
#pragma unroll
    for (int rr = 0; rr < 2; rr++) {
        int l = l0 + warp * 2 + rr;
        if (l >= L) continue;
        const float* row = feat + ((size_t)b * L + l) * 1024;
        float s = 0.f;
#pragma unroll
        for (int j = lane * 4; j < 1024; j += 128) {
            float4 f4 = *(const float4*)(row + j);
            s += tanh_hw(f4.x + sw[j + 0]) * vv[j + 0];
            s += tanh_hw(f4.y + sw[j + 1]) * vv[j + 1];
            s += tanh_hw(f4.z + sw[j + 2]) * vv[j + 2];
            s += tanh_hw(f4.w + sw[j + 3]) * vv[j + 3];
        }
#pragma unroll
        for (int o = 16; o > 0; o >>= 1) s += __shfl_xor_sync(0xffffffffu, s, o);
        if (lane == 0) eo[b * L + l] = s;
    }
}

// ---------------- masked renormalized softmax (per batch row) ----------------
__device__ void softmax_row(const float* __restrict__ e, const float* __restrict__ mask,
                            float* __restrict__ out, int L) {
    __shared__ float sbuf[S_];
    __shared__ float red[9];
    int t = threadIdx.x, w = t >> 5, ln = t & 31;
    float lm = -1e30f;
    for (int j = t; j < L; j += 256) { float v = e[j]; sbuf[j] = v; lm = fmaxf(lm, v); }
#pragma unroll
    for (int o = 16; o > 0; o >>= 1) lm = fmaxf(lm, __shfl_xor_sync(0xffffffffu, lm, o));
    if (ln == 0) red[w] = lm;
    __syncthreads();
    if (t == 0) { float m = red[0]; for (int i = 1; i < 8; i++) m = fmaxf(m, red[i]); red[8] = m; }
    __syncthreads();
    float M = red[8];
    float Z = 0.f, T = 0.f;
    for (int j = t; j < L; j += 256) {
        float p = __expf(sbuf[j] - M);
        float pm = p * mask[j];
        sbuf[j] = pm;
        Z += p; T += pm;
    }
#pragma unroll
    for (int o = 16; o > 0; o >>= 1) {
        Z += __shfl_xor_sync(0xffffffffu, Z, o);
        T += __shfl_xor_sync(0xffffffffu, T, o);
    }
    __syncthreads();
    if (ln == 0) red[w] = Z;
    __syncthreads();
    if (t == 0) { float s = 0.f; for (int i = 0; i < 8; i++) s += red[i]; red[8] = s; }
    __syncthreads();
    float Zs = red[8];
    __syncthreads();
    if (ln == 0) red[w] = T;
    __syncthreads();
    if (t == 0) { float s = 0.f; for (int i = 0; i < 8; i++) s += red[i]; red[8] = s; }
    __syncthreads();
    float Ts = red[8];
    float inv = 1.f / (Ts + 1e-12f * Zs);
    for (int j = t; j < L; j += 256) out[j] = sbuf[j] * inv;
    __syncthreads();
}

__global__ void att_softmax(const float* __restrict__ eE, const float* __restrict__ eX,
                            const float* __restrict__ maskE, const float* __restrict__ maskX,
                            float* __restrict__ attE, float* __restrict__ attX) {
    int b = blockIdx.x;
    softmax_row(eE + b * S_, maskE + b * S_, attE + b * S_, S_);
    softmax_row(eX + b * SX_, maskX + b * SX_, attX + b * SX_, SX_);
}

// ---------------- context vectors + c_t = logaddexp ----------------
// grid (64, 8): each block owns 128 d-values, l-range split across thread halves
__global__ __launch_bounds__(256)
void att_c(const float* __restrict__ attE, const float* __restrict__ attX,
           const float* __restrict__ encO, const float* __restrict__ xemO,
           float* __restrict__ ct_out, float* __restrict__ dec_cat) {
    int b = blockIdx.x, dch = blockIdx.y;
    __shared__ float aE[S_], aX[SX_];
    __shared__ float pE[256], pX[256];
    int t = threadIdx.x;
    for (int j = t; j < S_; j += 256) aE[j] = attE[b * S_ + j];
    for (int j = t; j < SX_; j += 256) aX[j] = attX[b * SX_ + j];
    __syncthreads();
    int d = dch * 128 + (t & 127);
    int half = t >> 7;
    float sE = 0.f, sX = 0.f;
    const float* pe = encO + (size_t)b * S_ * 1024 + d;
    int l0 = half * 200, l1 = l0 + 200;
#pragma unroll 8
    for (int l = l0; l < l1; l++) sE += aE[l] * pe[(size_t)l * 1024];
    const float* px = xemO + (size_t)b * SX_ * 1024 + d;
    int m0 = half * 100, m1 = m0 + 100;
#pragma unroll 10
    for (int l = m0; l < m1; l++) sX += aX[l] * px[(size_t)l * 1024];
    pE[t] = sE; pX[t] = sX;
    __syncthreads();
    if (t < 128) {
        float e = pE[t] + pE[t + 128];
        float x = pX[t] + pX[t + 128];
        float m = fmaxf(e, x);
        float ct = m + log1pf(expf(-fabsf(e - x)));
        int dd = dch * 128 + t;
        ct_out[b * 1024 + dd] = ct;
        dec_cat[b * 1536 + 512 + dd] = ct;
    }
}

// ---------------- vocab combine: per-batch (M, scale) from tile partials ----------------
__global__ __launch_bounds__(128)
void vocab_reduce(const float* __restrict__ vmax, const float* __restrict__ vsum,
                  const float* __restrict__ pgen,
                  float* __restrict__ vM, float* __restrict__ vscale) {
    int b = blockIdx.x, t = threadIdx.x;
    float m = -1e30f, s = 0.f;
    for (int tile = t; tile < NT_; tile += 128) {
        float m2 = vmax[tile * 64 + b];
        float s2 = vsum[tile * 64 + b];
        float M = fmaxf(m, m2);
        s = s * __expf(m - M) + s2 * __expf(m2 - M);
        m = M;
    }
#pragma unroll
    for (int o = 16; o > 0; o >>= 1) {
        float m2 = __shfl_xor_sync(0xffffffffu, m, o);
        float s2 = __shfl_xor_sync(0xffffffffu, s, o);
        float M = fmaxf(m, m2);
        s = s * __expf(m - M) + s2 * __expf(m2 - M);
        m = M;
    }
    __shared__ float sm[4], ss[4];
    if ((t & 31) == 0) { sm[t >> 5] = m; ss[t >> 5] = s; }
    __syncthreads();
    if (t == 0) {
        float M = sm[0], S = ss[0];
        for (int i = 1; i < 4; i++) {
            float M2 = fmaxf(M, sm[i]);
            S = S * __expf(M - M2) + ss[i] * __expf(sm[i] - M2);
            M = M2;
        }
        vM[b] = M;
        vscale[b] = pgen[b] / S;
    }
}

// ---------------- vocab write: final_dist vocab part + ext zeros ----------------
// grid (64, 8), 256 threads; chunk = 6375 outputs of the 51000-wide row
__global__ __launch_bounds__(256)
void vocab_write(const float* __restrict__ logits, const float* __restrict__ vM,
                 const float* __restrict__ vscale, const float* __restrict__ extz,
                 float* __restrict__ outF) {
    int b = blockIdx.x, ch = blockIdx.y, t = threadIdx.x;
    float M = vM[b], scale = vscale[b];
    const float* lg = logits + (size_t)b * V_;
    float* fd = outF + (size_t)b * (V_ + EXT_);
    int j0 = ch * 6375, j1 = j0 + 6375;
    for (int j = j0 + t; j < j1; j += 256) {
        if (j < V_) fd[j] = __expf(lg[j] - M) * scale;
        else fd[j] = extz[b * EXT_ + (j - V_)];
    }
}

// ---------------- scatter-add pointer distribution ----------------
__global__ void scatter_k(const float* __restrict__ attE, const int* __restrict__ idx,
                          const float* __restrict__ pgen, float* __restrict__ outF) {
    int b = blockIdx.x, l = threadIdx.x;
    float w = (1.f - pgen[b]) * attE[b * S_ + l];
    atomicAdd(&outF[(size_t)b * (V_ + EXT_) + idx[b * S_ + l]], w);
}

// ---------------- host ----------------
static float* symaddr(const void* s) {
    void* p = nullptr;
    cudaGetSymbolAddress(&p, s);
    return (float*)p;
}

extern "C" void kernel_launch(void* const* d_in, const int* in_sizes, int n_in,
                              void* d_out, int out_size) {
    const int*   y     = (const int*)d_in[0];
    const float* h0    = (const float*)d_in[1];
    const float* c0    = (const float*)d_in[2];
    const float* ct1   = (const float*)d_in[3];
    const float* encO  = (const float*)d_in[4];
    const float* encF  = (const float*)d_in[5];
    const float* maskE = (const float*)d_in[6];
    const float* xemO  = (const float*)d_in[7];
    const float* xemF  = (const float*)d_in[8];
    const float* maskX = (const float*)d_in[9];
    const float* extz  = (const float*)d_in[10];
    const int*   inpEx = (const int*)d_in[11];
    const float* emb   = (const float*)d_in[12];
    const float* Wxc   = (const float*)d_in[13];
    const float* bxc   = (const float*)d_in[14];
    const float* W_ih  = (const float*)d_in[15];
    const float* W_hh  = (const float*)d_in[16];
    const float* b_ih  = (const float*)d_in[17];
    const float* b_hh  = (const float*)d_in[18];
    const float* Ws_W  = (const float*)d_in[19];
    const float* Ws_b  = (const float*)d_in[20];
    const float* v_w   = (const float*)d_in[21];
    const float* V1_W  = (const float*)d_in[22];
    const float* V1_b  = (const float*)d_in[23];
    const float* V2_W  = (const float*)d_in[24];
    const float* V2_b  = (const float*)d_in[25];
    const float* pg_W  = (const float*)d_in[26];
    const float* pg_b  = (const float*)d_in[27];
    (void)in_sizes; (void)n_in; (void)out_size;

    float* out = (float*)d_out;
    float* o_final = out;                              // 64*51000
    float* o_h  = out + (size_t)B_ * (V_ + EXT_);      // 64*512
    float* o_c  = o_h + B_ * H_;                       // 64*512
    float* o_ct = o_c + B_ * H_;                       // 64*1024
    float* o_at = o_ct + B_ * 1024;                    // 64*400

    float* p_cat    = symaddr(g_cat);
    float* p_x      = symaddr(g_x);
    float* p_gates  = symaddr(g_gates);
    float* p_scat   = symaddr(g_scat);
    float* p_sws    = symaddr(g_sws);
    float* p_eE     = symaddr(g_eE);
    float* p_eX     = symaddr(g_eX);
    float* p_attX   = symaddr(g_attX);
    float* p_deccat = symaddr(g_deccat);
    float* p_z      = symaddr(g_z);
    float* p_logits = symaddr(g_logits);
    float* p_pgen   = symaddr(g_pgen);
    float* p_vmax   = symaddr(g_vmax);
    float* p_vsum   = symaddr(g_vsum);
    float* p_vM     = symaddr(g_vM);
    float* p_vscale = symaddr(g_vscale);

    // 0. cat = [emb[y], c_t_1] and all bias inits
    prep_init<<<B_, 256>>>(y, emb, ct1, bxc, b_ih, b_hh, Ws_b, V1_b,
                           p_cat, p_x, p_gates, p_sws, p_z);
    // 1. x = cat @ Wxc^T   (N=256, K=1280; split 16)
    gemm_mma<<<dim3(2, 16), 256>>>(p_cat, 1280, Wxc, nullptr, p_x, 256, 256, 1280, 16, 1,
                                   nullptr, nullptr);
    // 2. gates += x @ W_ih^T  and  h0 @ W_hh^T  (one dual launch)
    gemm_dual<<<dim3(16, 12), 256>>>(p_x, 256, W_ih, 256, 4,
                                     h0, 512, W_hh, 512, 8,
                                     p_gates, 2048, 2048);
    // 3. LSTM pointwise
    lstm_pw<<<B_, 512>>>(p_gates, c0, o_h, o_c, p_scat, p_deccat);
    // 4. s_ws = s_cat @ Ws_W^T (N=1024, K=1024; split 16)
    gemm_mma<<<dim3(8, 16), 256>>>(p_scat, 1024, Ws_W, nullptr, p_sws, 1024, 1024, 1024, 16, 1,
                                   nullptr, nullptr);
    // 5. attention scores (HW tanh)
    att_e<<<dim3(B_, 38), 256>>>(encF, xemF, p_sws, v_w, p_eE, p_eX);
    // 6. masked renormalized softmax
    att_softmax<<<B_, 256>>>(p_eE, p_eX, maskE, maskX, o_at, p_attX);
    // 7. contexts + c_t = logaddexp
    att_c<<<dim3(B_, 8), 256>>>(o_at, p_attX, encO, xemO, o_ct, p_deccat);
    // 8. z = dec_cat @ V1_W^T  +  p_gen (merged fat launch)
    v1_pgen<<<128, 256>>>(p_deccat, V1_W, p_z, o_ct, p_scat, p_cat, pg_W, pg_b, p_pgen);
    // 9. logits = z @ V2_W^T + V2_b (tf32 MMA) + per-tile softmax partials
    gemm_mma<<<dim3(NT_, 1), 256>>>(p_z, 512, V2_W, V2_b, p_logits, V_, V_, 512, 1, 2,
                                    p_vmax, p_vsum);
    // 10. combine partials -> per-batch M, scale
    vocab_reduce<<<B_, 128>>>(p_vmax, p_vsum, p_pgen, p_vM, p_vscale);
    // 11. write final vocab dist + ext zeros
    vocab_write<<<dim3(B_, 8), 256>>>(p_logits, p_vM, p_vscale, extz, o_final);
    // 12. scatter-add (1-p_gen)*attn
    scatter_k<<<B_, S_>>>(o_at, inpEx, p_pgen, o_final);
}